// round 13
// baseline (speedup 1.0000x reference)
#include <cuda_runtime.h>
#include <cstdint>

// BumpKNN R12: 3xTF32 mma.sync.m16n8k8. m32 per warp, 128-thr CTAs x4/SM,
// 3 independent depth-2 limb chains (HH/HL/LH) per row-block, permuted-k
// smem layout -> whole B fragment in one conflict-free LDS.128.
// Fused last-CTA bump finalize.

#define NQ      2048
#define ND      65536
#define STRIPS  16          // 2048 / 128 queries per CTA (4 warps x m32)
#define SPLITS  18          // 16*18 = 288 CTAs, 4 CTAs/SM co-resident
#define NTILE   128         // points per smem tile
#define THREADS 128
#define KPAD    20          // row stride (floats): conflict-free LDS.128

__device__ float g_partial[SPLITS * NQ];
__device__ unsigned int g_done;   // zero-init; reset by last CTA each run

__device__ __forceinline__ uint32_t f2tf(float x) {
    uint32_t r; asm("cvt.rna.tf32.f32 %0, %1;" : "=r"(r) : "f"(x)); return r;
}

__device__ __forceinline__ void mma8(float c[4], const uint32_t a[4],
                                     uint32_t b0, uint32_t b1) {
    asm("mma.sync.aligned.m16n8k8.row.col.f32.tf32.tf32.f32 "
        "{%0,%1,%2,%3}, {%4,%5,%6,%7}, {%8,%9}, {%0,%1,%2,%3};"
        : "+f"(c[0]), "+f"(c[1]), "+f"(c[2]), "+f"(c[3])
        : "r"(a[0]), "r"(a[1]), "r"(a[2]), "r"(a[3]), "r"(b0), "r"(b1));
}

// ---------------------------------------------------------------------------
__global__ void __launch_bounds__(THREADS, 4)
mma_kernel(const float* __restrict__ x, const float* __restrict__ data,
           float* __restrict__ out) {
    // Permuted-k rows: word slot 4*kc+j holds tf32(v[kc + 4*j]).
    __shared__ __align__(16) uint32_t sBhi[2][NTILE][KPAD];
    __shared__ __align__(16) uint32_t sBlo[2][NTILE][KPAD];
    __shared__ __align__(8)  float    sD2[2][NTILE];

    const int tid = threadIdx.x, lane = tid & 31, w = tid >> 5;
    const int strip = blockIdx.x, split = blockIdx.y;
    const int tiles = (split < 8) ? 29 : 28;       // 8*29 + 10*28 = 512 tiles
    const int tbase = (split < 8) ? 29 * split : 232 + 28 * (split - 8);

    const int g4 = lane >> 2, kc = lane & 3;
    const int qb = strip * 128 + w * 32;           // 32 query rows per warp

    // A fragments: -2*x tf32 hi/lo, [rowblock][kchunk].
    uint32_t ah[2][2][4], al[2][2][4];
#pragma unroll
    for (int rb = 0; rb < 2; rb++)
#pragma unroll
        for (int c = 0; c < 2; c++)
#pragma unroll
            for (int j = 0; j < 4; j++) {
                int row = qb + rb * 16 + g4 + (j & 1) * 8;
                int k   = c * 8 + kc + (j >> 1) * 4;
                float s = -2.f * __ldg(&x[(size_t)row * 16 + k]);
                uint32_t h = f2tf(s);
                ah[rb][c][j] = h;
                al[rb][c][j] = f2tf(s - __uint_as_float(h));
            }

    const float4* dv = reinterpret_cast<const float4*>(data);
    float4 r0, r1, r2, r3;   // prefetched point (r_i = dims 4i..4i+3)

    // Convert prefetched point -> permuted-k hi/lo rows + d2.
    // Block b of the row = {v[b], v[b+4], v[b+8], v[b+12]} = component b of
    // each prefetched float4.
    auto stash = [&](int buf) {
        uint4* ph = reinterpret_cast<uint4*>(&sBhi[buf][tid][0]);
        uint4* pl = reinterpret_cast<uint4*>(&sBlo[buf][tid][0]);
        float d2 = 0.f;
#pragma unroll
        for (int b = 0; b < 4; b++) {
            float v0, v1, v2, v3;
            if (b == 0) { v0 = r0.x; v1 = r1.x; v2 = r2.x; v3 = r3.x; }
            else if (b == 1) { v0 = r0.y; v1 = r1.y; v2 = r2.y; v3 = r3.y; }
            else if (b == 2) { v0 = r0.z; v1 = r1.z; v2 = r2.z; v3 = r3.z; }
            else { v0 = r0.w; v1 = r1.w; v2 = r2.w; v3 = r3.w; }
            d2 = fmaf(v0, v0, d2); d2 = fmaf(v1, v1, d2);
            d2 = fmaf(v2, v2, d2); d2 = fmaf(v3, v3, d2);
            uint32_t h0 = f2tf(v0), h1 = f2tf(v1), h2 = f2tf(v2), h3 = f2tf(v3);
            ph[b] = make_uint4(h0, h1, h2, h3);
            pl[b] = make_uint4(f2tf(v0 - __uint_as_float(h0)),
                               f2tf(v1 - __uint_as_float(h1)),
                               f2tf(v2 - __uint_as_float(h2)),
                               f2tf(v3 - __uint_as_float(h3)));
        }
        sD2[buf][tid] = d2;
    };

    {   // prologue: tile 0
        size_t p = (size_t)tbase * NTILE + tid;
        r0 = dv[p*4+0]; r1 = dv[p*4+1]; r2 = dv[p*4+2]; r3 = dv[p*4+3];
        stash(0);
    }
    __syncthreads();

    const float INF = 3.402823466e38f;
    float mn[8] = {INF, INF, INF, INF, INF, INF, INF, INF};

    for (int t = 0; t < tiles; t++) {
        const int buf = t & 1;
        if (t + 1 < tiles) {                      // prefetch next tile
            size_t p = (size_t)(tbase + t + 1) * NTILE + tid;
            r0 = dv[p*4+0]; r1 = dv[p*4+1]; r2 = dv[p*4+2]; r3 = dv[p*4+3];
        }

        const uint32_t* bh_ = &sBhi[buf][0][0];
        const uint32_t* bl_ = &sBlo[buf][0][0];
        const float*    d2_ = &sD2[buf][0];
#pragma unroll 4
        for (int it = 0; it < NTILE / 8; it++) {   // 16 n8 groups
            const int nb = it * 8;
            // Whole B fragment per limb in ONE LDS.128:
            // (x,y) = k-chunk0 (k=kc, kc+4); (z,w) = chunk1 (kc+8, kc+12).
            uint4 fh = *reinterpret_cast<const uint4*>(bh_ + (nb + g4) * KPAD + 4 * kc);
            uint4 fl = *reinterpret_cast<const uint4*>(bl_ + (nb + g4) * KPAD + 4 * kc);
            float2 dd = *reinterpret_cast<const float2*>(d2_ + nb + 2 * kc);

            // 6 chains: [rowblock] x {HH, HL, LH}, each depth 2 (k0 -> k1).
            float hh0[4] = {dd.x, dd.y, dd.x, dd.y};
            float hh1[4] = {dd.x, dd.y, dd.x, dd.y};
            float hl0[4] = {0.f, 0.f, 0.f, 0.f};
            float hl1[4] = {0.f, 0.f, 0.f, 0.f};
            float lh0[4] = {0.f, 0.f, 0.f, 0.f};
            float lh1[4] = {0.f, 0.f, 0.f, 0.f};

            // chain heads (k-chunk 0) — all independent
            mma8(hh0, ah[0][0], fh.x, fh.y);
            mma8(hh1, ah[1][0], fh.x, fh.y);
            mma8(hl0, ah[0][0], fl.x, fl.y);
            mma8(hl1, ah[1][0], fl.x, fl.y);
            mma8(lh0, al[0][0], fh.x, fh.y);
            mma8(lh1, al[1][0], fh.x, fh.y);
            // chain tails (k-chunk 1)
            mma8(hh0, ah[0][1], fh.z, fh.w);
            mma8(hh1, ah[1][1], fh.z, fh.w);
            mma8(hl0, ah[0][1], fl.z, fl.w);
            mma8(hl1, ah[1][1], fl.z, fl.w);
            mma8(lh0, al[0][1], fh.z, fh.w);
            mma8(lh1, al[1][1], fh.z, fh.w);

#pragma unroll
            for (int i = 0; i < 4; i++) {
                mn[i]     = fminf(mn[i],     hh0[i] + (hl0[i] + lh0[i]));
                mn[4 + i] = fminf(mn[4 + i], hh1[i] + (hl1[i] + lh1[i]));
            }
        }

        if (t + 1 < tiles) stash((t + 1) & 1);
        __syncthreads();
    }

    // Per-rowblock row mins; reduce across the 4 kc-lanes sharing each row.
#pragma unroll
    for (int rb = 0; rb < 2; rb++) {
        float rA = fminf(mn[rb * 4 + 0], mn[rb * 4 + 1]);
        float rB = fminf(mn[rb * 4 + 2], mn[rb * 4 + 3]);
        rA = fminf(rA, __shfl_xor_sync(0xffffffffu, rA, 1));
        rA = fminf(rA, __shfl_xor_sync(0xffffffffu, rA, 2));
        rB = fminf(rB, __shfl_xor_sync(0xffffffffu, rB, 1));
        rB = fminf(rB, __shfl_xor_sync(0xffffffffu, rB, 2));
        if (kc == 0) {
            int q = qb + rb * 16 + g4;
            g_partial[split * NQ + q]     = rA;   // = min(d2 - 2*dot)
            g_partial[split * NQ + q + 8] = rB;
        }
    }

    // ---- fused finalize: last CTA to arrive does the bump epilogue ----
    __threadfence();
    __shared__ unsigned int sLast;
    __syncthreads();
    if (tid == 0) sLast = atomicAdd(&g_done, 1u);
    __syncthreads();
    if (sLast == STRIPS * SPLITS - 1) {
        __threadfence();
        for (int q = tid; q < NQ; q += THREADS) {
            const float4* xp = reinterpret_cast<const float4*>(x + (size_t)q * 16);
            float4 a = xp[0], b = xp[1], c = xp[2], d = xp[3];
            float x2 = a.x*a.x + a.y*a.y + a.z*a.z + a.w*a.w
                     + b.x*b.x + b.y*b.y + b.z*b.z + b.w*b.w
                     + c.x*c.x + c.y*c.y + c.z*c.z + c.w*c.w
                     + d.x*d.x + d.y*d.y + d.z*d.z + d.w*d.w;
            float m = INF;
#pragma unroll
            for (int s = 0; s < SPLITS; s++)
                m = fminf(m, g_partial[s * NQ + q]);

            float nn2  = fmaxf(x2 + m, 0.0f);          // clamp tiny negatives
            float d2c  = fmaxf(nn2, 1e-12f);
            float dist = sqrtf(d2c);
            float r = 0.0f;
            if (dist < 2.0f) {                          // RADIUS = 2
                float ds = dist * dist;                 // reference sqrt->square
                r = expf(1.0f / (ds - 4.0f) + 0.25f);   // DECAY/denom + DECAY/r^2
            }
            out[q] = r;
        }
        __syncthreads();
        if (tid == 0) g_done = 0;                       // reset for next replay
    }
}

// ---------------------------------------------------------------------------
extern "C" void kernel_launch(void* const* d_in, const int* in_sizes, int n_in,
                              void* d_out, int out_size) {
    const float* x    = (const float*)d_in[0];
    const float* data = (const float*)d_in[1];
    if (n_in >= 2 && in_sizes[0] > in_sizes[1]) {  // defensive order check
        x    = (const float*)d_in[1];
        data = (const float*)d_in[0];
    }

    dim3 grid(STRIPS, SPLITS);
    mma_kernel<<<grid, THREADS>>>(x, data, (float*)d_out);
}

// round 14
// speedup vs baseline: 1.3408x; 1.3408x over previous
#include <cuda_runtime.h>
#include <cuda_fp16.h>
#include <cstdint>

// BumpKNN R13: 3xFP16 limb GEMM via mma.sync.m16n8k16.f16 (full-rate, K=16
// per instruction -> half the HMMAs of the tf32-k8 scheme whose ~50% tensor
// ceiling bound R8-R12). Same 11-bit-mantissa 2-limb math (HH + HL + LH),
// d2 in fp32 accumulator init, fused last-CTA bump finalize.

#define NQ      2048
#define ND      65536
#define STRIPS  16          // 2048 / 128 queries per CTA (8 warps x m16)
#define SPLITS  9           // 16*9 = 144 CTAs ~ one per SM
#define NTILE   128         // points per smem tile
#define THREADS 256

__device__ float g_partial[SPLITS * NQ];
__device__ unsigned int g_done;   // zero-init; reset by last CTA each run

// pack two f32 -> f16x2 {lo, hi} (PTX: first src -> hi)
__device__ __forceinline__ uint32_t h2pack(float lo, float hi) {
    uint32_t r; asm("cvt.rn.f16x2.f32 %0, %1, %2;" : "=r"(r) : "f"(hi), "f"(lo));
    return r;
}

__device__ __forceinline__ void mmaf16(float c[4], const uint32_t a[4],
                                       uint32_t b0, uint32_t b1) {
    asm("mma.sync.aligned.m16n8k16.row.col.f32.f16.f16.f32 "
        "{%0,%1,%2,%3}, {%4,%5,%6,%7}, {%8,%9}, {%0,%1,%2,%3};"
        : "+f"(c[0]), "+f"(c[1]), "+f"(c[2]), "+f"(c[3])
        : "r"(a[0]), "r"(a[1]), "r"(a[2]), "r"(a[3]), "r"(b0), "r"(b1));
}

// ---------------------------------------------------------------------------
__global__ void __launch_bounds__(THREADS)
mma_kernel(const float* __restrict__ x, const float* __restrict__ data,
           float* __restrict__ out) {
    // Per point: 16 words = 4 quads. Quad q holds, for kc = quad slot:
    // [whi[kc], whi[kc+4], wlo[kc], wlo[kc+4]]  (w[j] = half2(v[2j], v[2j+1]))
    // stored at physical quad ((kc + (p>>1)) & 3)  -> STS & LDS conflict-free.
    __shared__ __align__(16) uint32_t sB[2][NTILE][16];
    __shared__ __align__(8)  float    sD2[2][NTILE];

    const int tid = threadIdx.x, lane = tid & 31, w = tid >> 5;
    const int strip = blockIdx.x, split = blockIdx.y;
    const int tiles = (split < 8) ? 57 : 56;       // 8*57 + 56 = 512 tiles
    const int tbase = 57 * split;

    const int g4 = lane >> 2, kc = lane & 3;
    const int qb = strip * 128 + w * 16;           // 16 query rows per warp
    const int qsel = (kc + (g4 >> 1)) & 3;         // fragment quad (nb mult of 8)

    // A fragments (-2x): hi/lo half2. Order a0..a3 = (r0,k0)(r1,k0)(r0,k1)(r1,k1).
    uint32_t ah[4], al[4];
#pragma unroll
    for (int j = 0; j < 4; j++) {
        int row = qb + g4 + (j & 1) * 8;
        int k   = 2 * kc + (j >> 1) * 8;
        float s0 = -2.f * __ldg(&x[(size_t)row * 16 + k]);
        float s1 = -2.f * __ldg(&x[(size_t)row * 16 + k + 1]);
        uint32_t h = h2pack(s0, s1);
        __half2 hh = *reinterpret_cast<__half2*>(&h);
        ah[j] = h;
        al[j] = h2pack(s0 - __low2float(hh), s1 - __high2float(hh));
    }

    const float4* dv = reinterpret_cast<const float4*>(data);
    const bool loader = tid < NTILE;
    float4 r0, r1, r2, r3;

    // Convert prefetched point -> hi/lo half2 quads + d2.
    auto stash = [&](int buf) {
        float v[16] = {r0.x, r0.y, r0.z, r0.w, r1.x, r1.y, r1.z, r1.w,
                       r2.x, r2.y, r2.z, r2.w, r3.x, r3.y, r3.z, r3.w};
        float d2 = 0.f;
        uint32_t whi[8], wlo[8];
#pragma unroll
        for (int j = 0; j < 8; j++) {
            float v0 = v[2 * j], v1 = v[2 * j + 1];
            d2 = fmaf(v0, v0, d2);
            d2 = fmaf(v1, v1, d2);
            uint32_t h = h2pack(v0, v1);
            __half2 hh = *reinterpret_cast<__half2*>(&h);
            whi[j] = h;
            wlo[j] = h2pack(v0 - __low2float(hh), v1 - __high2float(hh));
        }
        uint4* row = reinterpret_cast<uint4*>(&sB[buf][tid][0]);
        const int rot = (tid >> 1) & 3;
#pragma unroll
        for (int q = 0; q < 4; q++)
            row[(q + rot) & 3] = make_uint4(whi[q], whi[q + 4], wlo[q], wlo[q + 4]);
        sD2[buf][tid] = d2;
    };

    if (loader) {   // prologue: tile 0
        size_t p = (size_t)tbase * NTILE + tid;
        r0 = dv[p*4+0]; r1 = dv[p*4+1]; r2 = dv[p*4+2]; r3 = dv[p*4+3];
        stash(0);
    }
    __syncthreads();

    const float INF = 3.402823466e38f;
    float m0 = INF, m1 = INF, m2 = INF, m3 = INF;

    for (int t = 0; t < tiles; t++) {
        const int buf = t & 1;
        if (t + 1 < tiles && loader) {            // prefetch next tile
            size_t p = (size_t)(tbase + t + 1) * NTILE + tid;
            r0 = dv[p*4+0]; r1 = dv[p*4+1]; r2 = dv[p*4+2]; r3 = dv[p*4+3];
        }

        const uint32_t* b_  = &sB[buf][0][0];
        const float*    d2_ = &sD2[buf][0];
#pragma unroll 8
        for (int it = 0; it < NTILE / 8; it++) {   // 16 n8 groups
            const int nb = it * 8;
            // Whole B fragment (hi+lo limbs) in ONE LDS.128:
            // f = {bh0, bh1, bl0, bl1}
            uint4 f = *reinterpret_cast<const uint4*>(b_ + (nb + g4) * 16 + 4 * qsel);
            float2 dd = *reinterpret_cast<const float2*>(d2_ + nb + 2 * kc);

            float chh[4] = {dd.x, dd.y, dd.x, dd.y};  // HH chain, d2 init
            float cl[4]  = {0.f, 0.f, 0.f, 0.f};      // HL + LH chain

            mmaf16(chh, ah, f.x, f.y);   // Ah * Bh   (independent)
            mmaf16(cl,  ah, f.z, f.w);   // Ah * Bl
            mmaf16(cl,  al, f.x, f.y);   // Al * Bh   (serial on cl only)

            m0 = fminf(m0, chh[0] + cl[0]);
            m1 = fminf(m1, chh[1] + cl[1]);
            m2 = fminf(m2, chh[2] + cl[2]);
            m3 = fminf(m3, chh[3] + cl[3]);
        }

        if (t + 1 < tiles && loader) stash((t + 1) & 1);
        __syncthreads();
    }

    // Row mins: c0/c1 -> row g4, c2/c3 -> row g4+8; reduce across the 4
    // kc-lanes sharing each row.
    float rA = fminf(m0, m1);
    float rB = fminf(m2, m3);
    rA = fminf(rA, __shfl_xor_sync(0xffffffffu, rA, 1));
    rA = fminf(rA, __shfl_xor_sync(0xffffffffu, rA, 2));
    rB = fminf(rB, __shfl_xor_sync(0xffffffffu, rB, 1));
    rB = fminf(rB, __shfl_xor_sync(0xffffffffu, rB, 2));
    if (kc == 0) {
        g_partial[split * NQ + qb + g4]     = rA;  // = min(d2 - 2*dot)
        g_partial[split * NQ + qb + g4 + 8] = rB;
    }

    // ---- fused finalize: last CTA to arrive does the bump epilogue ----
    __threadfence();
    __shared__ unsigned int sLast;
    __syncthreads();
    if (tid == 0) sLast = atomicAdd(&g_done, 1u);
    __syncthreads();
    if (sLast == STRIPS * SPLITS - 1) {
        __threadfence();
        for (int q = tid; q < NQ; q += THREADS) {
            const float4* xp = reinterpret_cast<const float4*>(x + (size_t)q * 16);
            float4 a = xp[0], b = xp[1], c = xp[2], d = xp[3];
            float x2 = a.x*a.x + a.y*a.y + a.z*a.z + a.w*a.w
                     + b.x*b.x + b.y*b.y + b.z*b.z + b.w*b.w
                     + c.x*c.x + c.y*c.y + c.z*c.z + c.w*c.w
                     + d.x*d.x + d.y*d.y + d.z*d.z + d.w*d.w;
            float m = INF;
#pragma unroll
            for (int s = 0; s < SPLITS; s++)
                m = fminf(m, g_partial[s * NQ + q]);

            float nn2  = fmaxf(x2 + m, 0.0f);          // clamp tiny negatives
            float d2c  = fmaxf(nn2, 1e-12f);
            float dist = sqrtf(d2c);
            float r = 0.0f;
            if (dist < 2.0f) {                          // RADIUS = 2
                float ds = dist * dist;                 // reference sqrt->square
                r = expf(1.0f / (ds - 4.0f) + 0.25f);   // DECAY/denom + DECAY/r^2
            }
            out[q] = r;
        }
        __syncthreads();
        if (tid == 0) g_done = 0;                       // reset for next replay
    }
}

// ---------------------------------------------------------------------------
extern "C" void kernel_launch(void* const* d_in, const int* in_sizes, int n_in,
                              void* d_out, int out_size) {
    const float* x    = (const float*)d_in[0];
    const float* data = (const float*)d_in[1];
    if (n_in >= 2 && in_sizes[0] > in_sizes[1]) {  // defensive order check
        x    = (const float*)d_in[1];
        data = (const float*)d_in[0];
    }

    dim3 grid(STRIPS, SPLITS);
    mma_kernel<<<grid, THREADS>>>(x, data, (float*)d_out);
}

// round 15
// speedup vs baseline: 1.6298x; 1.2155x over previous
#include <cuda_runtime.h>
#include <cuda_fp16.h>
#include <cstdint>

// BumpKNN R14: fp16 m16n8k16 3-limb GEMM, m32 per warp (B fragment feeds 6
// HMMAs), 6 fully-independent accumulation chains per group -> dependency
// latency off the critical path (R13 binder: tensor=33% @ 2-chain serial).
// Fused last-CTA bump finalize.

#define NQ      2048
#define ND      65536
#define STRIPS  8           // 2048 / 256 queries per CTA (8 warps x m32)
#define SPLITS  18          // 8*18 = 144 CTAs ~ one per SM
#define NTILE   128         // points per smem tile
#define THREADS 256

__device__ float g_partial[SPLITS * NQ];
__device__ unsigned int g_done;   // zero-init; reset by last CTA each run

// pack two f32 -> f16x2 {lo, hi} (PTX: first src -> hi)
__device__ __forceinline__ uint32_t h2pack(float lo, float hi) {
    uint32_t r; asm("cvt.rn.f16x2.f32 %0, %1, %2;" : "=r"(r) : "f"(hi), "f"(lo));
    return r;
}

__device__ __forceinline__ void mmaf16(float c[4], const uint32_t a[4],
                                       uint32_t b0, uint32_t b1) {
    asm("mma.sync.aligned.m16n8k16.row.col.f32.f16.f16.f32 "
        "{%0,%1,%2,%3}, {%4,%5,%6,%7}, {%8,%9}, {%0,%1,%2,%3};"
        : "+f"(c[0]), "+f"(c[1]), "+f"(c[2]), "+f"(c[3])
        : "r"(a[0]), "r"(a[1]), "r"(a[2]), "r"(a[3]), "r"(b0), "r"(b1));
}

// ---------------------------------------------------------------------------
__global__ void __launch_bounds__(THREADS)
mma_kernel(const float* __restrict__ x, const float* __restrict__ data,
           float* __restrict__ out) {
    // Per point: 16 words = 4 quads. Logical quad kc holds
    // [whi[kc], whi[kc+4], wlo[kc], wlo[kc+4]]  (w[j] = half2(v[2j], v[2j+1])),
    // stored at physical quad ((kc + (p>>1)) & 3) -> STS & LDS conflict-free.
    __shared__ __align__(16) uint32_t sB[2][NTILE][16];
    __shared__ __align__(8)  float    sD2[2][NTILE];

    const int tid = threadIdx.x, lane = tid & 31, w = tid >> 5;
    const int strip = blockIdx.x, split = blockIdx.y;
    const int tiles = (split < 8) ? 29 : 28;       // 8*29 + 10*28 = 512 tiles
    const int tbase = (split < 8) ? 29 * split : 232 + 28 * (split - 8);

    const int g4 = lane >> 2, kc = lane & 3;
    const int qb = strip * 256 + w * 32;           // 32 query rows per warp
    const int qsel = (kc + (g4 >> 1)) & 3;         // fragment quad (nb mult of 8)

    // A fragments (-2x): hi/lo half2, [rowblock][j];
    // j order = (r0,k0)(r1,k0)(r0,k1)(r1,k1).
    uint32_t ah[2][4], al[2][4];
#pragma unroll
    for (int rb = 0; rb < 2; rb++)
#pragma unroll
        for (int j = 0; j < 4; j++) {
            int row = qb + rb * 16 + g4 + (j & 1) * 8;
            int k   = 2 * kc + (j >> 1) * 8;
            float s0 = -2.f * __ldg(&x[(size_t)row * 16 + k]);
            float s1 = -2.f * __ldg(&x[(size_t)row * 16 + k + 1]);
            uint32_t h = h2pack(s0, s1);
            __half2 hh = *reinterpret_cast<__half2*>(&h);
            ah[rb][j] = h;
            al[rb][j] = h2pack(s0 - __low2float(hh), s1 - __high2float(hh));
        }

    const float4* dv = reinterpret_cast<const float4*>(data);
    const bool loader = tid < NTILE;
    float4 r0, r1, r2, r3;

    // Convert prefetched point -> hi/lo half2 quads + d2.
    auto stash = [&](int buf) {
        float v[16] = {r0.x, r0.y, r0.z, r0.w, r1.x, r1.y, r1.z, r1.w,
                       r2.x, r2.y, r2.z, r2.w, r3.x, r3.y, r3.z, r3.w};
        float d2 = 0.f;
        uint32_t whi[8], wlo[8];
#pragma unroll
        for (int j = 0; j < 8; j++) {
            float v0 = v[2 * j], v1 = v[2 * j + 1];
            d2 = fmaf(v0, v0, d2);
            d2 = fmaf(v1, v1, d2);
            uint32_t h = h2pack(v0, v1);
            __half2 hh = *reinterpret_cast<__half2*>(&h);
            whi[j] = h;
            wlo[j] = h2pack(v0 - __low2float(hh), v1 - __high2float(hh));
        }
        uint4* row = reinterpret_cast<uint4*>(&sB[buf][tid][0]);
        const int rot = (tid >> 1) & 3;
#pragma unroll
        for (int q = 0; q < 4; q++)
            row[(q + rot) & 3] = make_uint4(whi[q], whi[q + 4], wlo[q], wlo[q + 4]);
        sD2[buf][tid] = d2;
    };

    if (loader) {   // prologue: tile 0
        size_t p = (size_t)tbase * NTILE + tid;
        r0 = dv[p*4+0]; r1 = dv[p*4+1]; r2 = dv[p*4+2]; r3 = dv[p*4+3];
        stash(0);
    }
    __syncthreads();

    const float INF = 3.402823466e38f;
    float mn[8] = {INF, INF, INF, INF, INF, INF, INF, INF};

    for (int t = 0; t < tiles; t++) {
        const int buf = t & 1;
        if (t + 1 < tiles && loader) {            // prefetch next tile
            size_t p = (size_t)(tbase + t + 1) * NTILE + tid;
            r0 = dv[p*4+0]; r1 = dv[p*4+1]; r2 = dv[p*4+2]; r3 = dv[p*4+3];
        }

        const uint32_t* b_  = &sB[buf][0][0];
        const float*    d2_ = &sD2[buf][0];
#pragma unroll 4
        for (int it = 0; it < NTILE / 8; it++) {   // 16 n8 groups
            const int nb = it * 8;
            // Whole B fragment (hi+lo limbs) in ONE LDS.128:
            // f = {bh0, bh1, bl0, bl1}
            uint4 f = *reinterpret_cast<const uint4*>(b_ + (nb + g4) * 16 + 4 * qsel);
            float2 dd = *reinterpret_cast<const float2*>(d2_ + nb + 2 * kc);

            // 6 fully-independent chains: [rowblock] x {HH, HL, LH}.
            float hh0[4] = {dd.x, dd.y, dd.x, dd.y};
            float hh1[4] = {dd.x, dd.y, dd.x, dd.y};
            float hl0[4] = {0.f, 0.f, 0.f, 0.f};
            float hl1[4] = {0.f, 0.f, 0.f, 0.f};
            float lh0[4] = {0.f, 0.f, 0.f, 0.f};
            float lh1[4] = {0.f, 0.f, 0.f, 0.f};

            mmaf16(hh0, ah[0], f.x, f.y);   // Ah0 * Bh
            mmaf16(hh1, ah[1], f.x, f.y);   // Ah1 * Bh
            mmaf16(hl0, ah[0], f.z, f.w);   // Ah0 * Bl
            mmaf16(hl1, ah[1], f.z, f.w);   // Ah1 * Bl
            mmaf16(lh0, al[0], f.x, f.y);   // Al0 * Bh
            mmaf16(lh1, al[1], f.x, f.y);   // Al1 * Bh

#pragma unroll
            for (int i = 0; i < 4; i++) {
                mn[i]     = fminf(mn[i],     hh0[i] + (hl0[i] + lh0[i]));
                mn[4 + i] = fminf(mn[4 + i], hh1[i] + (hl1[i] + lh1[i]));
            }
        }

        if (t + 1 < tiles && loader) stash((t + 1) & 1);
        __syncthreads();
    }

    // Per-rowblock row mins; reduce across the 4 kc-lanes sharing each row.
#pragma unroll
    for (int rb = 0; rb < 2; rb++) {
        float rA = fminf(mn[rb * 4 + 0], mn[rb * 4 + 1]);
        float rB = fminf(mn[rb * 4 + 2], mn[rb * 4 + 3]);
        rA = fminf(rA, __shfl_xor_sync(0xffffffffu, rA, 1));
        rA = fminf(rA, __shfl_xor_sync(0xffffffffu, rA, 2));
        rB = fminf(rB, __shfl_xor_sync(0xffffffffu, rB, 1));
        rB = fminf(rB, __shfl_xor_sync(0xffffffffu, rB, 2));
        if (kc == 0) {
            int q = qb + rb * 16 + g4;
            g_partial[split * NQ + q]     = rA;   // = min(d2 - 2*dot)
            g_partial[split * NQ + q + 8] = rB;
        }
    }

    // ---- fused finalize: last CTA to arrive does the bump epilogue ----
    __threadfence();
    __shared__ unsigned int sLast;
    __syncthreads();
    if (tid == 0) sLast = atomicAdd(&g_done, 1u);
    __syncthreads();
    if (sLast == STRIPS * SPLITS - 1) {
        __threadfence();
        for (int q = tid; q < NQ; q += THREADS) {
            const float4* xp = reinterpret_cast<const float4*>(x + (size_t)q * 16);
            float4 a = xp[0], b = xp[1], c = xp[2], d = xp[3];
            float x2 = a.x*a.x + a.y*a.y + a.z*a.z + a.w*a.w
                     + b.x*b.x + b.y*b.y + b.z*b.z + b.w*b.w
                     + c.x*c.x + c.y*c.y + c.z*c.z + c.w*c.w
                     + d.x*d.x + d.y*d.y + d.z*d.z + d.w*d.w;
            float m = INF;
#pragma unroll
            for (int s = 0; s < SPLITS; s++)
                m = fminf(m, g_partial[s * NQ + q]);

            float nn2  = fmaxf(x2 + m, 0.0f);          // clamp tiny negatives
            float d2c  = fmaxf(nn2, 1e-12f);
            float dist = sqrtf(d2c);
            float r = 0.0f;
            if (dist < 2.0f) {                          // RADIUS = 2
                float ds = dist * dist;                 // reference sqrt->square
                r = expf(1.0f / (ds - 4.0f) + 0.25f);   // DECAY/denom + DECAY/r^2
            }
            out[q] = r;
        }
        __syncthreads();
        if (tid == 0) g_done = 0;                       // reset for next replay
    }
}

// ---------------------------------------------------------------------------
extern "C" void kernel_launch(void* const* d_in, const int* in_sizes, int n_in,
                              void* d_out, int out_size) {
    const float* x    = (const float*)d_in[0];
    const float* data = (const float*)d_in[1];
    if (n_in >= 2 && in_sizes[0] > in_sizes[1]) {  // defensive order check
        x    = (const float*)d_in[1];
        data = (const float*)d_in[0];
    }

    dim3 grid(STRIPS, SPLITS);
    mma_kernel<<<grid, THREADS>>>(x, data, (float*)d_out);
}

// round 16
// speedup vs baseline: 1.7091x; 1.0487x over previous
#include <cuda_runtime.h>
#include <cuda_fp16.h>
#include <cstdint>

// BumpKNN R15: R14 (fp16 m16n8k16 3-limb, m32/warp, 6 independent chains)
// with 2 CTAs/SM (grid 288, __launch_bounds__(256,2)). R14 binder was warp
// supply: tensor=39% @ occ=12.6%, issue=45%, regs=74, smem=17KB -> 2 CTAs fit.

#define NQ      2048
#define ND      65536
#define STRIPS  8           // 2048 / 256 queries per CTA (8 warps x m32)
#define SPLITS  36          // 8*36 = 288 CTAs ~ 2 per SM
#define NTILE   128         // points per smem tile
#define THREADS 256

__device__ float g_partial[SPLITS * NQ];
__device__ unsigned int g_done;   // zero-init; reset by last CTA each run

// pack two f32 -> f16x2 {lo, hi} (PTX: first src -> hi)
__device__ __forceinline__ uint32_t h2pack(float lo, float hi) {
    uint32_t r; asm("cvt.rn.f16x2.f32 %0, %1, %2;" : "=r"(r) : "f"(hi), "f"(lo));
    return r;
}

__device__ __forceinline__ void mmaf16(float c[4], const uint32_t a[4],
                                       uint32_t b0, uint32_t b1) {
    asm("mma.sync.aligned.m16n8k16.row.col.f32.f16.f16.f32 "
        "{%0,%1,%2,%3}, {%4,%5,%6,%7}, {%8,%9}, {%0,%1,%2,%3};"
        : "+f"(c[0]), "+f"(c[1]), "+f"(c[2]), "+f"(c[3])
        : "r"(a[0]), "r"(a[1]), "r"(a[2]), "r"(a[3]), "r"(b0), "r"(b1));
}

// ---------------------------------------------------------------------------
__global__ void __launch_bounds__(THREADS, 2)
mma_kernel(const float* __restrict__ x, const float* __restrict__ data,
           float* __restrict__ out) {
    // Per point: 16 words = 4 quads. Logical quad kc holds
    // [whi[kc], whi[kc+4], wlo[kc], wlo[kc+4]]  (w[j] = half2(v[2j], v[2j+1])),
    // stored at physical quad ((kc + (p>>1)) & 3) -> STS & LDS conflict-free.
    __shared__ __align__(16) uint32_t sB[2][NTILE][16];
    __shared__ __align__(8)  float    sD2[2][NTILE];

    const int tid = threadIdx.x, lane = tid & 31, w = tid >> 5;
    const int strip = blockIdx.x, split = blockIdx.y;
    const int tiles = (split < 8) ? 15 : 14;       // 8*15 + 28*14 = 512 tiles
    const int tbase = (split < 8) ? 15 * split : 120 + 14 * (split - 8);

    const int g4 = lane >> 2, kc = lane & 3;
    const int qb = strip * 256 + w * 32;           // 32 query rows per warp
    const int qsel = (kc + (g4 >> 1)) & 3;         // fragment quad (nb mult of 8)

    // A fragments (-2x): hi/lo half2, [rowblock][j];
    // j order = (r0,k0)(r1,k0)(r0,k1)(r1,k1).
    uint32_t ah[2][4], al[2][4];
#pragma unroll
    for (int rb = 0; rb < 2; rb++)
#pragma unroll
        for (int j = 0; j < 4; j++) {
            int row = qb + rb * 16 + g4 + (j & 1) * 8;
            int k   = 2 * kc + (j >> 1) * 8;
            float s0 = -2.f * __ldg(&x[(size_t)row * 16 + k]);
            float s1 = -2.f * __ldg(&x[(size_t)row * 16 + k + 1]);
            uint32_t h = h2pack(s0, s1);
            __half2 hh = *reinterpret_cast<__half2*>(&h);
            ah[rb][j] = h;
            al[rb][j] = h2pack(s0 - __low2float(hh), s1 - __high2float(hh));
        }

    const float4* dv = reinterpret_cast<const float4*>(data);
    const bool loader = tid < NTILE;
    float4 r0, r1, r2, r3;

    // Convert prefetched point -> hi/lo half2 quads + d2.
    auto stash = [&](int buf) {
        float v[16] = {r0.x, r0.y, r0.z, r0.w, r1.x, r1.y, r1.z, r1.w,
                       r2.x, r2.y, r2.z, r2.w, r3.x, r3.y, r3.z, r3.w};
        float d2 = 0.f;
        uint32_t whi[8], wlo[8];
#pragma unroll
        for (int j = 0; j < 8; j++) {
            float v0 = v[2 * j], v1 = v[2 * j + 1];
            d2 = fmaf(v0, v0, d2);
            d2 = fmaf(v1, v1, d2);
            uint32_t h = h2pack(v0, v1);
            __half2 hh = *reinterpret_cast<__half2*>(&h);
            whi[j] = h;
            wlo[j] = h2pack(v0 - __low2float(hh), v1 - __high2float(hh));
        }
        uint4* row = reinterpret_cast<uint4*>(&sB[buf][tid][0]);
        const int rot = (tid >> 1) & 3;
#pragma unroll
        for (int q = 0; q < 4; q++)
            row[(q + rot) & 3] = make_uint4(whi[q], whi[q + 4], wlo[q], wlo[q + 4]);
        sD2[buf][tid] = d2;
    };

    if (loader) {   // prologue: tile 0
        size_t p = (size_t)tbase * NTILE + tid;
        r0 = dv[p*4+0]; r1 = dv[p*4+1]; r2 = dv[p*4+2]; r3 = dv[p*4+3];
        stash(0);
    }
    __syncthreads();

    const float INF = 3.402823466e38f;
    float mn[8] = {INF, INF, INF, INF, INF, INF, INF, INF};

    for (int t = 0; t < tiles; t++) {
        const int buf = t & 1;
        if (t + 1 < tiles && loader) {            // prefetch next tile
            size_t p = (size_t)(tbase + t + 1) * NTILE + tid;
            r0 = dv[p*4+0]; r1 = dv[p*4+1]; r2 = dv[p*4+2]; r3 = dv[p*4+3];
        }

        const uint32_t* b_  = &sB[buf][0][0];
        const float*    d2_ = &sD2[buf][0];
#pragma unroll 4
        for (int it = 0; it < NTILE / 8; it++) {   // 16 n8 groups
            const int nb = it * 8;
            // Whole B fragment (hi+lo limbs) in ONE LDS.128:
            // f = {bh0, bh1, bl0, bl1}
            uint4 f = *reinterpret_cast<const uint4*>(b_ + (nb + g4) * 16 + 4 * qsel);
            float2 dd = *reinterpret_cast<const float2*>(d2_ + nb + 2 * kc);

            // 6 fully-independent chains: [rowblock] x {HH, HL, LH}.
            float hh0[4] = {dd.x, dd.y, dd.x, dd.y};
            float hh1[4] = {dd.x, dd.y, dd.x, dd.y};
            float hl0[4] = {0.f, 0.f, 0.f, 0.f};
            float hl1[4] = {0.f, 0.f, 0.f, 0.f};
            float lh0[4] = {0.f, 0.f, 0.f, 0.f};
            float lh1[4] = {0.f, 0.f, 0.f, 0.f};

            mmaf16(hh0, ah[0], f.x, f.y);   // Ah0 * Bh
            mmaf16(hh1, ah[1], f.x, f.y);   // Ah1 * Bh
            mmaf16(hl0, ah[0], f.z, f.w);   // Ah0 * Bl
            mmaf16(hl1, ah[1], f.z, f.w);   // Ah1 * Bl
            mmaf16(lh0, al[0], f.x, f.y);   // Al0 * Bh
            mmaf16(lh1, al[1], f.x, f.y);   // Al1 * Bh

#pragma unroll
            for (int i = 0; i < 4; i++) {
                mn[i]     = fminf(mn[i],     hh0[i] + (hl0[i] + lh0[i]));
                mn[4 + i] = fminf(mn[4 + i], hh1[i] + (hl1[i] + lh1[i]));
            }
        }

        if (t + 1 < tiles && loader) stash((t + 1) & 1);
        __syncthreads();
    }

    // Per-rowblock row mins; reduce across the 4 kc-lanes sharing each row.
#pragma unroll
    for (int rb = 0; rb < 2; rb++) {
        float rA = fminf(mn[rb * 4 + 0], mn[rb * 4 + 1]);
        float rB = fminf(mn[rb * 4 + 2], mn[rb * 4 + 3]);
        rA = fminf(rA, __shfl_xor_sync(0xffffffffu, rA, 1));
        rA = fminf(rA, __shfl_xor_sync(0xffffffffu, rA, 2));
        rB = fminf(rB, __shfl_xor_sync(0xffffffffu, rB, 1));
        rB = fminf(rB, __shfl_xor_sync(0xffffffffu, rB, 2));
        if (kc == 0) {
            int q = qb + rb * 16 + g4;
            g_partial[split * NQ + q]     = rA;   // = min(d2 - 2*dot)
            g_partial[split * NQ + q + 8] = rB;
        }
    }

    // ---- fused finalize: last CTA to arrive does the bump epilogue ----
    __threadfence();
    __shared__ unsigned int sLast;
    __syncthreads();
    if (tid == 0) sLast = atomicAdd(&g_done, 1u);
    __syncthreads();
    if (sLast == STRIPS * SPLITS - 1) {
        __threadfence();
        for (int q = tid; q < NQ; q += THREADS) {
            const float4* xp = reinterpret_cast<const float4*>(x + (size_t)q * 16);
            float4 a = xp[0], b = xp[1], c = xp[2], d = xp[3];
            float x2 = a.x*a.x + a.y*a.y + a.z*a.z + a.w*a.w
                     + b.x*b.x + b.y*b.y + b.z*b.z + b.w*b.w
                     + c.x*c.x + c.y*c.y + c.z*c.z + c.w*c.w
                     + d.x*d.x + d.y*d.y + d.z*d.z + d.w*d.w;
            float m = INF;
#pragma unroll
            for (int s = 0; s < SPLITS; s++)
                m = fminf(m, g_partial[s * NQ + q]);

            float nn2  = fmaxf(x2 + m, 0.0f);          // clamp tiny negatives
            float d2c  = fmaxf(nn2, 1e-12f);
            float dist = sqrtf(d2c);
            float r = 0.0f;
            if (dist < 2.0f) {                          // RADIUS = 2
                float ds = dist * dist;                 // reference sqrt->square
                r = expf(1.0f / (ds - 4.0f) + 0.25f);   // DECAY/denom + DECAY/r^2
            }
            out[q] = r;
        }
        __syncthreads();
        if (tid == 0) g_done = 0;                       // reset for next replay
    }
}

// ---------------------------------------------------------------------------
extern "C" void kernel_launch(void* const* d_in, const int* in_sizes, int n_in,
                              void* d_out, int out_size) {
    const float* x    = (const float*)d_in[0];
    const float* data = (const float*)d_in[1];
    if (n_in >= 2 && in_sizes[0] > in_sizes[1]) {  // defensive order check
        x    = (const float*)d_in[1];
        data = (const float*)d_in[0];
    }

    dim3 grid(STRIPS, SPLITS);
    mma_kernel<<<grid, THREADS>>>(x, data, (float*)d_out);
}

// round 17
// speedup vs baseline: 1.7642x; 1.0322x over previous
#include <cuda_runtime.h>
#include <cuda_fp16.h>
#include <cstdint>

// BumpKNN R16: R15 shape (fp16 m16n8k16, m32/warp, 2 CTAs/SM, 288 CTAs)
// with the two limb-correction chains (HL, LH) merged into ONE serial HMMA
// accumulator -> 8 fewer FADDs per n8-group (epilogue fma work halves).
// R15 binder: scalar epilogue stream (fma 17% + alu 26%) vs tensor 42%.

#define NQ      2048
#define ND      65536
#define STRIPS  8           // 2048 / 256 queries per CTA (8 warps x m32)
#define SPLITS  36          // 8*36 = 288 CTAs ~ 2 per SM
#define NTILE   128         // points per smem tile
#define THREADS 256

__device__ float g_partial[SPLITS * NQ];
__device__ unsigned int g_done;   // zero-init; reset by last CTA each run

// pack two f32 -> f16x2 {lo, hi} (PTX: first src -> hi)
__device__ __forceinline__ uint32_t h2pack(float lo, float hi) {
    uint32_t r; asm("cvt.rn.f16x2.f32 %0, %1, %2;" : "=r"(r) : "f"(hi), "f"(lo));
    return r;
}

__device__ __forceinline__ void mmaf16(float c[4], const uint32_t a[4],
                                       uint32_t b0, uint32_t b1) {
    asm("mma.sync.aligned.m16n8k16.row.col.f32.f16.f16.f32 "
        "{%0,%1,%2,%3}, {%4,%5,%6,%7}, {%8,%9}, {%0,%1,%2,%3};"
        : "+f"(c[0]), "+f"(c[1]), "+f"(c[2]), "+f"(c[3])
        : "r"(a[0]), "r"(a[1]), "r"(a[2]), "r"(a[3]), "r"(b0), "r"(b1));
}

// ---------------------------------------------------------------------------
__global__ void __launch_bounds__(THREADS, 2)
mma_kernel(const float* __restrict__ x, const float* __restrict__ data,
           float* __restrict__ out) {
    // Per point: 16 words = 4 quads. Logical quad kc holds
    // [whi[kc], whi[kc+4], wlo[kc], wlo[kc+4]]  (w[j] = half2(v[2j], v[2j+1])),
    // stored at physical quad ((kc + (p>>1)) & 3) -> STS & LDS conflict-free.
    __shared__ __align__(16) uint32_t sB[2][NTILE][16];
    __shared__ __align__(8)  float    sD2[2][NTILE];

    const int tid = threadIdx.x, lane = tid & 31, w = tid >> 5;
    const int strip = blockIdx.x, split = blockIdx.y;
    const int tiles = (split < 8) ? 15 : 14;       // 8*15 + 28*14 = 512 tiles
    const int tbase = (split < 8) ? 15 * split : 120 + 14 * (split - 8);

    const int g4 = lane >> 2, kc = lane & 3;
    const int qb = strip * 256 + w * 32;           // 32 query rows per warp
    const int qsel = (kc + (g4 >> 1)) & 3;         // fragment quad (nb mult of 8)

    // A fragments (-2x): hi/lo half2, [rowblock][j];
    // j order = (r0,k0)(r1,k0)(r0,k1)(r1,k1).
    uint32_t ah[2][4], al[2][4];
#pragma unroll
    for (int rb = 0; rb < 2; rb++)
#pragma unroll
        for (int j = 0; j < 4; j++) {
            int row = qb + rb * 16 + g4 + (j & 1) * 8;
            int k   = 2 * kc + (j >> 1) * 8;
            float s0 = -2.f * __ldg(&x[(size_t)row * 16 + k]);
            float s1 = -2.f * __ldg(&x[(size_t)row * 16 + k + 1]);
            uint32_t h = h2pack(s0, s1);
            __half2 hh = *reinterpret_cast<__half2*>(&h);
            ah[rb][j] = h;
            al[rb][j] = h2pack(s0 - __low2float(hh), s1 - __high2float(hh));
        }

    const float4* dv = reinterpret_cast<const float4*>(data);
    const bool loader = tid < NTILE;
    float4 r0, r1, r2, r3;

    // Convert prefetched point -> hi/lo half2 quads + d2.
    auto stash = [&](int buf) {
        float v[16] = {r0.x, r0.y, r0.z, r0.w, r1.x, r1.y, r1.z, r1.w,
                       r2.x, r2.y, r2.z, r2.w, r3.x, r3.y, r3.z, r3.w};
        float d2 = 0.f;
        uint32_t whi[8], wlo[8];
#pragma unroll
        for (int j = 0; j < 8; j++) {
            float v0 = v[2 * j], v1 = v[2 * j + 1];
            d2 = fmaf(v0, v0, d2);
            d2 = fmaf(v1, v1, d2);
            uint32_t h = h2pack(v0, v1);
            __half2 hh = *reinterpret_cast<__half2*>(&h);
            whi[j] = h;
            wlo[j] = h2pack(v0 - __low2float(hh), v1 - __high2float(hh));
        }
        uint4* row = reinterpret_cast<uint4*>(&sB[buf][tid][0]);
        const int rot = (tid >> 1) & 3;
#pragma unroll
        for (int q = 0; q < 4; q++)
            row[(q + rot) & 3] = make_uint4(whi[q], whi[q + 4], wlo[q], wlo[q + 4]);
        sD2[buf][tid] = d2;
    };

    if (loader) {   // prologue: tile 0
        size_t p = (size_t)tbase * NTILE + tid;
        r0 = dv[p*4+0]; r1 = dv[p*4+1]; r2 = dv[p*4+2]; r3 = dv[p*4+3];
        stash(0);
    }
    __syncthreads();

    const float INF = 3.402823466e38f;
    float mn[8] = {INF, INF, INF, INF, INF, INF, INF, INF};

    for (int t = 0; t < tiles; t++) {
        const int buf = t & 1;
        if (t + 1 < tiles && loader) {            // prefetch next tile
            size_t p = (size_t)(tbase + t + 1) * NTILE + tid;
            r0 = dv[p*4+0]; r1 = dv[p*4+1]; r2 = dv[p*4+2]; r3 = dv[p*4+3];
        }

        const uint32_t* b_  = &sB[buf][0][0];
        const float*    d2_ = &sD2[buf][0];
#pragma unroll 4
        for (int it = 0; it < NTILE / 8; it++) {   // 16 n8 groups
            const int nb = it * 8;
            // Whole B fragment (hi+lo limbs) in ONE LDS.128:
            // f = {bh0, bh1, bl0, bl1}
            uint4 f = *reinterpret_cast<const uint4*>(b_ + (nb + g4) * 16 + 4 * qsel);
            float2 dd = *reinterpret_cast<const float2*>(d2_ + nb + 2 * kc);

            // 4 chains: [rowblock] x {HH (d2 init), CL = HL then LH serial}.
            float hh0[4] = {dd.x, dd.y, dd.x, dd.y};
            float hh1[4] = {dd.x, dd.y, dd.x, dd.y};
            float cl0[4] = {0.f, 0.f, 0.f, 0.f};
            float cl1[4] = {0.f, 0.f, 0.f, 0.f};

            mmaf16(hh0, ah[0], f.x, f.y);   // Ah0 * Bh   (independent)
            mmaf16(hh1, ah[1], f.x, f.y);   // Ah1 * Bh   (independent)
            mmaf16(cl0, ah[0], f.z, f.w);   // Ah0 * Bl
            mmaf16(cl1, ah[1], f.z, f.w);   // Ah1 * Bl
            mmaf16(cl0, al[0], f.x, f.y);   // Al0 * Bh   (serial on cl0)
            mmaf16(cl1, al[1], f.x, f.y);   // Al1 * Bh   (serial on cl1)

#pragma unroll
            for (int i = 0; i < 4; i++) {
                mn[i]     = fminf(mn[i],     hh0[i] + cl0[i]);
                mn[4 + i] = fminf(mn[4 + i], hh1[i] + cl1[i]);
            }
        }

        if (t + 1 < tiles && loader) stash((t + 1) & 1);
        __syncthreads();
    }

    // Per-rowblock row mins; reduce across the 4 kc-lanes sharing each row.
#pragma unroll
    for (int rb = 0; rb < 2; rb++) {
        float rA = fminf(mn[rb * 4 + 0], mn[rb * 4 + 1]);
        float rB = fminf(mn[rb * 4 + 2], mn[rb * 4 + 3]);
        rA = fminf(rA, __shfl_xor_sync(0xffffffffu, rA, 1));
        rA = fminf(rA, __shfl_xor_sync(0xffffffffu, rA, 2));
        rB = fminf(rB, __shfl_xor_sync(0xffffffffu, rB, 1));
        rB = fminf(rB, __shfl_xor_sync(0xffffffffu, rB, 2));
        if (kc == 0) {
            int q = qb + rb * 16 + g4;
            g_partial[split * NQ + q]     = rA;   // = min(d2 - 2*dot)
            g_partial[split * NQ + q + 8] = rB;
        }
    }

    // ---- fused finalize: last CTA to arrive does the bump epilogue ----
    __threadfence();
    __shared__ unsigned int sLast;
    __syncthreads();
    if (tid == 0) sLast = atomicAdd(&g_done, 1u);
    __syncthreads();
    if (sLast == STRIPS * SPLITS - 1) {
        __threadfence();
        for (int q = tid; q < NQ; q += THREADS) {
            const float4* xp = reinterpret_cast<const float4*>(x + (size_t)q * 16);
            float4 a = xp[0], b = xp[1], c = xp[2], d = xp[3];
            float x2 = a.x*a.x + a.y*a.y + a.z*a.z + a.w*a.w
                     + b.x*b.x + b.y*b.y + b.z*b.z + b.w*b.w
                     + c.x*c.x + c.y*c.y + c.z*c.z + c.w*c.w
                     + d.x*d.x + d.y*d.y + d.z*d.z + d.w*d.w;
            float m = INF;
#pragma unroll
            for (int s = 0; s < SPLITS; s++)
                m = fminf(m, g_partial[s * NQ + q]);

            float nn2  = fmaxf(x2 + m, 0.0f);          // clamp tiny negatives
            float d2c  = fmaxf(nn2, 1e-12f);
            float dist = sqrtf(d2c);
            float r = 0.0f;
            if (dist < 2.0f) {                          // RADIUS = 2
                float ds = dist * dist;                 // reference sqrt->square
                r = expf(1.0f / (ds - 4.0f) + 0.25f);   // DECAY/denom + DECAY/r^2
            }
            out[q] = r;
        }
        __syncthreads();
        if (tid == 0) g_done = 0;                       // reset for next replay
    }
}

// ---------------------------------------------------------------------------
extern "C" void kernel_launch(void* const* d_in, const int* in_sizes, int n_in,
                              void* d_out, int out_size) {
    const float* x    = (const float*)d_in[0];
    const float* data = (const float*)d_in[1];
    if (n_in >= 2 && in_sizes[0] > in_sizes[1]) {  // defensive order check
        x    = (const float*)d_in[1];
        data = (const float*)d_in[0];
    }

    dim3 grid(STRIPS, SPLITS);
    mma_kernel<<<grid, THREADS>>>(x, data, (float*)d_out);
}